// round 3
// baseline (speedup 1.0000x reference)
#include <cuda_runtime.h>
#include <cstdint>

// Shapes (fixed by the problem)
#define T_TOK 4096      // B*S
#define H_DIM 2048
#define I_DIM 8192
#define EPSF  1e-5f
#define WCNT  (I_DIM * H_DIM)     // 16777216 elements in each weight matrix
#define WN4   (WCNT / 4)

// -------------------- device scratch (no allocations allowed) --------------------
__device__ int8_t g_xq[T_TOK * H_DIM];
__device__ float  g_sx[T_TOK];
__device__ int8_t g_wgq[I_DIM * H_DIM];
__device__ int8_t g_wuq[I_DIM * H_DIM];
__device__ int8_t g_wdq[H_DIM * I_DIM];
__device__ float  g_y[(size_t)T_TOK * I_DIM];      // 134 MB intermediate
__device__ int8_t g_yq[(size_t)T_TOK * I_DIM];
__device__ float  g_sy[T_TOK];
__device__ float  g_partials[3][1024];
__device__ float  g_wscale[3];

// -------------------- weight absmean reduction (deterministic 2-pass) --------------------
__global__ void abssum_kernel(const float4* __restrict__ w4, int slot) {
    float s = 0.f;
    for (int i = blockIdx.x * 256 + threadIdx.x; i < WN4; i += 1024 * 256) {
        float4 v = w4[i];
        s += fabsf(v.x) + fabsf(v.y) + fabsf(v.z) + fabsf(v.w);
    }
    __shared__ float red[256];
    red[threadIdx.x] = s;
    __syncthreads();
    for (int o = 128; o > 0; o >>= 1) {
        if (threadIdx.x < o) red[threadIdx.x] += red[threadIdx.x + o];
        __syncthreads();
    }
    if (threadIdx.x == 0) g_partials[slot][blockIdx.x] = red[0];
}

__global__ void wscale_finalize_kernel() {
    __shared__ float red[1024];
    for (int slot = 0; slot < 3; slot++) {
        red[threadIdx.x] = g_partials[slot][threadIdx.x];
        __syncthreads();
        for (int o = 512; o > 0; o >>= 1) {
            if (threadIdx.x < o) red[threadIdx.x] += red[threadIdx.x + o];
            __syncthreads();
        }
        if (threadIdx.x == 0)
            g_wscale[slot] = fmaxf(red[0] * (1.0f / (float)WCNT), EPSF);
        __syncthreads();
    }
}

// -------------------- ternary weight quantization --------------------
// NOTE: plain `char` is UNSIGNED on aarch64 — must go through int -> signed char,
// otherwise all -1 weights saturate to 0 (the round-2 bug).
__global__ void quantw_kernel(const float4* __restrict__ w4, int slot) {
    int i = blockIdx.x * blockDim.x + threadIdx.x;
    if (i >= WN4) return;
    int8_t* dst = (slot == 0) ? g_wgq : (slot == 1) ? g_wuq : g_wdq;
    float inv = 1.0f / g_wscale[slot];
    float4 v = w4[i];
    int rx = __float2int_rn(v.x * inv);
    int ry = __float2int_rn(v.y * inv);
    int rz = __float2int_rn(v.z * inv);
    int rw = __float2int_rn(v.w * inv);
    rx = max(-1, min(1, rx));
    ry = max(-1, min(1, ry));
    rz = max(-1, min(1, rz));
    rw = max(-1, min(1, rw));
    char4 o;
    o.x = (signed char)rx;
    o.y = (signed char)ry;
    o.z = (signed char)rz;
    o.w = (signed char)rw;
    ((char4*)dst)[i] = o;
}

// -------------------- FWHT + per-token absmax int8 quant --------------------
// One block per token. Butterfly order matches the reference's reshape structure.
template <int N>
__global__ void fwht_quant_kernel(const float* __restrict__ x_ext) {
    __shared__ float s[N];
    __shared__ float red[256];
    const int t = threadIdx.x;
    const size_t base = (size_t)blockIdx.x * N;

    const float* src = (N == 2048) ? x_ext : (const float*)g_y;
    int8_t* q = (N == 2048) ? g_xq : g_yq;
    float* sout = (N == 2048) ? g_sx : g_sy;

    const float4* x4 = (const float4*)(src + base);
    float4* s4 = (float4*)s;
#pragma unroll
    for (int i = t; i < N / 4; i += 256) s4[i] = x4[i];
    __syncthreads();

    for (int h = 1; h < N; h <<= 1) {
        for (int p = t; p < N / 2; p += 256) {
            int i = ((p & ~(h - 1)) << 1) | (p & (h - 1));
            int j = i + h;
            float a = s[i], b = s[j];
            s[i] = a + b;
            s[j] = a - b;
        }
        __syncthreads();
    }

    const float norm = (N == 2048) ? 0.02209708691207961f   // 1/sqrt(2048)
                                   : 0.011048543456039806f; // 1/sqrt(8192)
    float m = 0.f;
    for (int i = t; i < N; i += 256) {
        float v = s[i] * norm;
        s[i] = v;
        m = fmaxf(m, fabsf(v));
    }
    red[t] = m;
    __syncthreads();
    for (int o = 128; o > 0; o >>= 1) {
        if (t < o) red[t] = fmaxf(red[t], red[t + o]);
        __syncthreads();
    }
    float mx = fmaxf(red[0], EPSF);
    float scale = 127.0f / mx;
    if (t == 0) sout[blockIdx.x] = mx * (1.0f / 127.0f);   // = 1/scale
    for (int i = t; i < N; i += 256) {
        int r = __float2int_rn(s[i] * scale);    // round half-even then clip, like ref
        r = max(-128, min(127, r));
        q[base + i] = (int8_t)r;
    }
}

// -------------------- IMMA helper --------------------
__device__ __forceinline__ void mma_s8(int* c, const unsigned* a, unsigned b0, unsigned b1) {
    asm volatile(
        "mma.sync.aligned.m16n8k32.row.col.s32.s8.s8.s32 "
        "{%0,%1,%2,%3}, {%4,%5,%6,%7}, {%8,%9}, {%0,%1,%2,%3};\n"
        : "+r"(c[0]), "+r"(c[1]), "+r"(c[2]), "+r"(c[3])
        : "r"(a[0]), "r"(a[1]), "r"(a[2]), "r"(a[3]), "r"(b0), "r"(b1));
}

__device__ __forceinline__ float silu_mul(float gate, float up) {
    return (gate / (1.0f + expf(-gate))) * up;
}

// -------------------- GEMM1: fused gate+up, BM=128 BN=64 BK=64 --------------------
// y[t][o] = silu(Sg * swg * sx[t]) * (Su * swu * sx[t])
__global__ __launch_bounds__(256) void gemm1_kernel() {
    __shared__ int8_t As[128 * 80];
    __shared__ int8_t Bg[64 * 80];
    __shared__ int8_t Bu[64 * 80];

    const int tid = threadIdx.x;
    const int wid = tid >> 5, lane = tid & 31;
    const int g = lane >> 2, tig = lane & 3;
    const int warpM = wid & 3;   // 4 warps over M, 32 rows each
    const int warpN = wid >> 2;  // 2 warps over N, 32 cols each
    const int blockM = blockIdx.y * 128;
    const int blockN = blockIdx.x * 64;

    int acc_g[2][4][4], acc_u[2][4][4];
#pragma unroll
    for (int a = 0; a < 2; a++)
#pragma unroll
        for (int b = 0; b < 4; b++)
#pragma unroll
            for (int c = 0; c < 4; c++) { acc_g[a][b][c] = 0; acc_u[a][b][c] = 0; }

    const int ldr = tid >> 2;        // 0..63
    const int ldc = (tid & 3) << 4;  // 0,16,32,48

    for (int k0 = 0; k0 < H_DIM; k0 += 64) {
        *(int4*)&As[ldr * 80 + ldc] =
            *(const int4*)&g_xq[(size_t)(blockM + ldr) * H_DIM + k0 + ldc];
        *(int4*)&As[(ldr + 64) * 80 + ldc] =
            *(const int4*)&g_xq[(size_t)(blockM + ldr + 64) * H_DIM + k0 + ldc];
        *(int4*)&Bg[ldr * 80 + ldc] =
            *(const int4*)&g_wgq[(size_t)(blockN + ldr) * H_DIM + k0 + ldc];
        *(int4*)&Bu[ldr * 80 + ldc] =
            *(const int4*)&g_wuq[(size_t)(blockN + ldr) * H_DIM + k0 + ldc];
        __syncthreads();
#pragma unroll
        for (int kk = 0; kk < 64; kk += 32) {
            unsigned a[2][4];
#pragma unroll
            for (int mt = 0; mt < 2; mt++) {
                int r = warpM * 32 + mt * 16 + g;
                a[mt][0] = *(const unsigned*)&As[r * 80 + kk + tig * 4];
                a[mt][1] = *(const unsigned*)&As[(r + 8) * 80 + kk + tig * 4];
                a[mt][2] = *(const unsigned*)&As[r * 80 + kk + 16 + tig * 4];
                a[mt][3] = *(const unsigned*)&As[(r + 8) * 80 + kk + 16 + tig * 4];
            }
#pragma unroll
            for (int nt = 0; nt < 4; nt++) {
                int c = warpN * 32 + nt * 8 + g;
                unsigned bg0 = *(const unsigned*)&Bg[c * 80 + kk + tig * 4];
                unsigned bg1 = *(const unsigned*)&Bg[c * 80 + kk + 16 + tig * 4];
                unsigned bu0 = *(const unsigned*)&Bu[c * 80 + kk + tig * 4];
                unsigned bu1 = *(const unsigned*)&Bu[c * 80 + kk + 16 + tig * 4];
#pragma unroll
                for (int mt = 0; mt < 2; mt++) {
                    mma_s8(acc_g[mt][nt], a[mt], bg0, bg1);
                    mma_s8(acc_u[mt][nt], a[mt], bu0, bu1);
                }
            }
        }
        __syncthreads();
    }

    const float swg = g_wscale[0], swu = g_wscale[1];
#pragma unroll
    for (int mt = 0; mt < 2; mt++) {
        int r0 = blockM + warpM * 32 + mt * 16 + g;
        float sx0 = g_sx[r0], sx1 = g_sx[r0 + 8];
        float fg0 = swg * sx0, fu0 = swu * sx0;
        float fg1 = swg * sx1, fu1 = swu * sx1;
#pragma unroll
        for (int nt = 0; nt < 4; nt++) {
            int c0 = blockN + warpN * 32 + nt * 8 + tig * 2;
            size_t o00 = (size_t)r0 * I_DIM + c0;
            size_t o10 = (size_t)(r0 + 8) * I_DIM + c0;
            g_y[o00]     = silu_mul((float)acc_g[mt][nt][0] * fg0, (float)acc_u[mt][nt][0] * fu0);
            g_y[o00 + 1] = silu_mul((float)acc_g[mt][nt][1] * fg0, (float)acc_u[mt][nt][1] * fu0);
            g_y[o10]     = silu_mul((float)acc_g[mt][nt][2] * fg1, (float)acc_u[mt][nt][2] * fu1);
            g_y[o10 + 1] = silu_mul((float)acc_g[mt][nt][3] * fg1, (float)acc_u[mt][nt][3] * fu1);
        }
    }
}

// -------------------- GEMM2: down proj, BM=128 BN=128 BK=64, K=8192 --------------------
__global__ __launch_bounds__(256) void gemm2_kernel(float* __restrict__ out) {
    __shared__ int8_t As[128 * 80];
    __shared__ int8_t Bs[128 * 80];

    const int tid = threadIdx.x;
    const int wid = tid >> 5, lane = tid & 31;
    const int g = lane >> 2, tig = lane & 3;
    const int warpM = wid & 1;   // 2 warps over M, 64 rows each
    const int warpN = wid >> 1;  // 4 warps over N, 32 cols each
    const int blockM = blockIdx.y * 128;
    const int blockN = blockIdx.x * 128;

    int acc[4][4][4];
#pragma unroll
    for (int a = 0; a < 4; a++)
#pragma unroll
        for (int b = 0; b < 4; b++)
#pragma unroll
            for (int c = 0; c < 4; c++) acc[a][b][c] = 0;

    const int ldr = tid >> 2;
    const int ldc = (tid & 3) << 4;

    for (int k0 = 0; k0 < I_DIM; k0 += 64) {
        *(int4*)&As[ldr * 80 + ldc] =
            *(const int4*)&g_yq[(size_t)(blockM + ldr) * I_DIM + k0 + ldc];
        *(int4*)&As[(ldr + 64) * 80 + ldc] =
            *(const int4*)&g_yq[(size_t)(blockM + ldr + 64) * I_DIM + k0 + ldc];
        *(int4*)&Bs[ldr * 80 + ldc] =
            *(const int4*)&g_wdq[(size_t)(blockN + ldr) * I_DIM + k0 + ldc];
        *(int4*)&Bs[(ldr + 64) * 80 + ldc] =
            *(const int4*)&g_wdq[(size_t)(blockN + ldr + 64) * I_DIM + k0 + ldc];
        __syncthreads();
#pragma unroll
        for (int kk = 0; kk < 64; kk += 32) {
            unsigned a[4][4];
#pragma unroll
            for (int mt = 0; mt < 4; mt++) {
                int r = warpM * 64 + mt * 16 + g;
                a[mt][0] = *(const unsigned*)&As[r * 80 + kk + tig * 4];
                a[mt][1] = *(const unsigned*)&As[(r + 8) * 80 + kk + tig * 4];
                a[mt][2] = *(const unsigned*)&As[r * 80 + kk + 16 + tig * 4];
                a[mt][3] = *(const unsigned*)&As[(r + 8) * 80 + kk + 16 + tig * 4];
            }
#pragma unroll
            for (int nt = 0; nt < 4; nt++) {
                int c = warpN * 32 + nt * 8 + g;
                unsigned b0 = *(const unsigned*)&Bs[c * 80 + kk + tig * 4];
                unsigned b1 = *(const unsigned*)&Bs[c * 80 + kk + 16 + tig * 4];
#pragma unroll
                for (int mt = 0; mt < 4; mt++) mma_s8(acc[mt][nt], a[mt], b0, b1);
            }
        }
        __syncthreads();
    }

    const float swd = g_wscale[2];
#pragma unroll
    for (int mt = 0; mt < 4; mt++) {
        int r0 = blockM + warpM * 64 + mt * 16 + g;
        float f0 = swd * g_sy[r0];
        float f1 = swd * g_sy[r0 + 8];
#pragma unroll
        for (int nt = 0; nt < 4; nt++) {
            int c0 = blockN + warpN * 32 + nt * 8 + tig * 2;
            out[(size_t)r0 * H_DIM + c0]           = (float)acc[mt][nt][0] * f0;
            out[(size_t)r0 * H_DIM + c0 + 1]       = (float)acc[mt][nt][1] * f0;
            out[(size_t)(r0 + 8) * H_DIM + c0]     = (float)acc[mt][nt][2] * f1;
            out[(size_t)(r0 + 8) * H_DIM + c0 + 1] = (float)acc[mt][nt][3] * f1;
        }
    }
}

// -------------------- launch --------------------
extern "C" void kernel_launch(void* const* d_in, const int* in_sizes, int n_in,
                              void* d_out, int out_size) {
    const float* x  = (const float*)d_in[0];
    const float* wg = (const float*)d_in[1];
    const float* wu = (const float*)d_in[2];
    const float* wd = (const float*)d_in[3];
    float* out = (float*)d_out;

    // 1. ternary weight quantization (deterministic mean reduction)
    abssum_kernel<<<1024, 256>>>((const float4*)wg, 0);
    abssum_kernel<<<1024, 256>>>((const float4*)wu, 1);
    abssum_kernel<<<1024, 256>>>((const float4*)wd, 2);
    wscale_finalize_kernel<<<1, 1024>>>();
    quantw_kernel<<<WN4 / 256, 256>>>((const float4*)wg, 0);
    quantw_kernel<<<WN4 / 256, 256>>>((const float4*)wu, 1);
    quantw_kernel<<<WN4 / 256, 256>>>((const float4*)wd, 2);

    // 2. FWHT(2048) + act quant
    fwht_quant_kernel<2048><<<T_TOK, 256>>>(x);

    // 3. fused gate+up int8 GEMM + SiLU*up epilogue
    gemm1_kernel<<<dim3(I_DIM / 64, T_TOK / 128), 256>>>();

    // 4. FWHT(8192) + act quant
    fwht_quant_kernel<8192><<<T_TOK, 256>>>(nullptr);

    // 5. down int8 GEMM + final scaling
    gemm2_kernel<<<dim3(H_DIM / 128, T_TOK / 128), 256>>>(out);
}